// round 6
// baseline (speedup 1.0000x reference)
#include <cuda_runtime.h>

#define TPB 256

constexpr int B_     = 16384;
constexpr int N_     = 70;
constexpr int STEPS_ = 5;
constexpr int BB_    = 16;

constexpr int XPLANE = 568;   // u64 per X s-plane (70*8 + 8 pad)
constexpr int PPLANE = 560;   // u64 per P d-plane

// ---- shared memory layout (float offsets) ----
constexpr int OFF_X   = 0;            // 10 planes * 1136 = 11360
constexpr int OFF_P   = 11360;        // 10 planes * 1120 = 11200
constexpr int OFF_AS  = 22560;        // A half-chunk, up to 70*36 = 2520
constexpr int OFF_WIN = 25080;        // dup [e][d][s]: 300 u64 = 600
constexpr int OFF_BIN = 25680;        // dup [e][s]: 30 u64 = 60
constexpr int OFF_WR  = 25740;        // dup [j][s]: 200 u64 = 400
constexpr int OFF_WZ  = 26140;        // 400
constexpr int OFF_WH  = 26540;        // 400
constexpr int OFF_BR  = 26940;        // 10 u64 = 20
constexpr int OFF_BZ  = 26960;        // 20
constexpr int OFF_BH  = 26980;        // 20
constexpr int OFF_WO1 = 27000;        // 110
constexpr int OFF_BO1 = 27110;        // 10
constexpr int OFF_WO2 = 27120;        // 10
constexpr int OFF_BO2 = 27130;        // 1
constexpr int SMEM_FLOATS = 27131;    // 108524 B/CTA -> 2 CTAs/SM

typedef unsigned long long u64;

// ---- packed f32x2 helpers ----
__device__ __forceinline__ u64 ffma2(u64 a, u64 b, u64 c) {
    u64 d;
    asm("fma.rn.f32x2 %0, %1, %2, %3;" : "=l"(d) : "l"(a), "l"(b), "l"(c));
    return d;
}
__device__ __forceinline__ u64 mul2(u64 a, u64 b) {
    u64 d;
    asm("mul.rn.f32x2 %0, %1, %2;" : "=l"(d) : "l"(a), "l"(b));
    return d;
}
__device__ __forceinline__ u64 pack2(float x) {
    u64 d;
    asm("mov.b64 %0, {%1, %1};" : "=l"(d) : "f"(x));
    return d;
}
__device__ __forceinline__ u64 packxy(float x, float y) {
    u64 d;
    asm("mov.b64 %0, {%1, %2};" : "=l"(d) : "f"(x), "f"(y));
    return d;
}
__device__ __forceinline__ void unpack2(u64 v, float& x, float& y) {
    asm("mov.b64 {%0, %1}, %2;" : "=f"(x), "=f"(y) : "l"(v));
}

__device__ __forceinline__ float sigf(float x) {
    return __fdividef(1.0f, 1.0f + __expf(-x));
}
__device__ __forceinline__ float tanh_(float x) {
    float e = __expf(-2.0f * x);
    return __fdividef(1.0f - e, 1.0f + e);
}

extern __shared__ float sm[];

// ---- stage A[:, e*70+k0 : +KC] chunk into SMEM (scalar, row-major) ----
template <int KC>
__device__ __forceinline__ void stageA(const float* __restrict__ Ag, int e,
                                       int k0, int t) {
#pragma unroll 1
    for (int i = t; i < 70 * KC; i += TPB) {
        int row = i / KC, kk = i - row * KC;
        sm[OFF_AS + i] = Ag[row * 210 + e * 70 + k0 + kk];
    }
}

// ---- GEMM partial: rows {ty,ty+16,ty+32,ty+48[,64+ty]}, row-serialized ----
// A-words consumed one row at a time to keep live set ~128 regs (no spills).
template <int NK2, int R>
__device__ __forceinline__ void gemm_part(u64 (&acc)[5][5], const u64* xk,
                                          int ty) {
    const u64* As2 = (const u64*)(sm + OFF_AS);
    const int r0 = ty * NK2;
#pragma unroll 1
    for (int kk = 0; kk < NK2; ++kk) {
        const u64* xr = xk + kk * 16;
        u64 xE[5], xO[5];
#pragma unroll
        for (int j = 0; j < 5; ++j) {
            xE[j] = xr[j * (2 * XPLANE)];
            xO[j] = xr[8 + j * (2 * XPLANE)];
        }
#pragma unroll
        for (int i = 0; i < 4; ++i) {
            u64 aw = As2[r0 + i * (16 * NK2) + kk];
            float lo, hi;
            unpack2(aw, lo, hi);
            u64 pE = pack2(lo);
#pragma unroll
            for (int j = 0; j < 5; ++j)
                acc[i][j] = ffma2(pE, xE[j], acc[i][j]);
            u64 pO = pack2(hi);
#pragma unroll
            for (int j = 0; j < 5; ++j)
                acc[i][j] = ffma2(pO, xO[j], acc[i][j]);
        }
        if (R == 5) {
            u64 aw = As2[(64 + ty) * NK2 + kk];
            float lo, hi;
            unpack2(aw, lo, hi);
            u64 pE = pack2(lo);
#pragma unroll
            for (int j = 0; j < 5; ++j)
                acc[4][j] = ffma2(pE, xE[j], acc[4][j]);
            u64 pO = pack2(hi);
#pragma unroll
            for (int j = 0; j < 5; ++j)
                acc[4][j] = ffma2(pO, xO[j], acc[4][j]);
        }
    }
}

__global__ void __launch_bounds__(TPB, 2) ggnn_kernel(
    const float* __restrict__ annotation, const float* __restrict__ Ag,
    const float* __restrict__ W_in, const float* __restrict__ b_in,
    const float* __restrict__ Wr, const float* __restrict__ br,
    const float* __restrict__ Wz, const float* __restrict__ bz,
    const float* __restrict__ Wh, const float* __restrict__ bh,
    const float* __restrict__ Wo1, const float* __restrict__ bo1,
    const float* __restrict__ Wo2, const float* __restrict__ bo2,
    float* __restrict__ out)
{
    const int t  = threadIdx.x;
    const int b0 = blockIdx.x * BB_;

    // ---- stage duplicated weight tables ----
    for (int i = t; i < 300; i += TPB) {          // WIN dup [e][d][s]
        int e = i / 100, r = i - e * 100;
        int d = r / 10, s = r - d * 10;
        float v = W_in[(e * 10 + s) * 10 + d];
        ((float2*)(sm + OFF_WIN))[i] = make_float2(v, v);
    }
    if (t < 30) {                                 // BIN dup [e][s]
        float v = b_in[t];
        ((float2*)(sm + OFF_BIN))[t] = make_float2(v, v);
    }
    for (int i = t; i < 200; i += TPB) {          // W{r,z,h} dup [j][s]
        int j = i / 10, s = i - j * 10;
        float v;
        v = Wr[s * 20 + j]; ((float2*)(sm + OFF_WR))[i] = make_float2(v, v);
        v = Wz[s * 20 + j]; ((float2*)(sm + OFF_WZ))[i] = make_float2(v, v);
        v = Wh[s * 20 + j]; ((float2*)(sm + OFF_WH))[i] = make_float2(v, v);
    }
    if (t < 10) {
        float v;
        v = br[t]; ((float2*)(sm + OFF_BR))[t] = make_float2(v, v);
        v = bz[t]; ((float2*)(sm + OFF_BZ))[t] = make_float2(v, v);
        v = bh[t]; ((float2*)(sm + OFF_BH))[t] = make_float2(v, v);
        sm[OFF_BO1 + t] = bo1[t];
        sm[OFF_WO2 + t] = Wo2[t];
    }
    for (int i = t; i < 110; i += TPB) sm[OFF_WO1 + i] = Wo1[i];
    if (t == 0) sm[OFF_BO2] = bo2[0];

    // ---- prop init: P[0][n*16+bb] = ann, rest 0 ----
    for (int i = t; i < BB_ * N_; i += TPB) {
        int bb = i / N_, n = i - bb * N_;
        float a = annotation[b0 * N_ + i];
        sm[OFF_P + n * 16 + bb] = a;
#pragma unroll
        for (int d = 1; d < 10; ++d) sm[OFF_P + d * 1120 + n * 16 + bb] = 0.0f;
    }
    __syncthreads();

    const int tx  = t & 15;          // column group
    const int ty  = t >> 4;          // row group (0..15)
    const int txh = tx >> 3;         // X plane parity
    const int bpx = tx & 7;          // batch-pair within plane
    const bool r5 = (ty < 6);        // 5th GEMM row valid

    u64 acc[5][5];

#pragma unroll 1
    for (int step = 0; step < STEPS_; ++step) {
#pragma unroll
        for (int i = 0; i < 5; ++i)
#pragma unroll
            for (int j = 0; j < 5; ++j) acc[i][j] = 0ull;

#pragma unroll 1
        for (int e = 0; e < 3; ++e) {
            // stage A first half + build X (both write-only, disjoint)
            stageA<36>(Ag, e, 0, t);
            // ---- build X[s][n*8+bbp] = ins (batch-paired, MOV-free) ----
#pragma unroll 1
            for (int task = t; task < 560; task += TPB) {
                int n = task >> 3, bbp = task & 7;
                const u64* Pu = (const u64*)(sm + OFF_P) + n * 8 + bbp;
                const u64* Bi = (const u64*)(sm + OFF_BIN) + e * 10;
                u64 a[10];
#pragma unroll
                for (int s = 0; s < 10; ++s) a[s] = Bi[s];
                const ulonglong2* W =
                    (const ulonglong2*)((const u64*)(sm + OFF_WIN) + e * 100);
#pragma unroll
                for (int d = 0; d < 10; ++d) {
                    u64 pv = Pu[d * PPLANE];
#pragma unroll
                    for (int q = 0; q < 5; ++q) {
                        ulonglong2 w = W[d * 5 + q];
                        a[2 * q]     = ffma2(pv, w.x, a[2 * q]);
                        a[2 * q + 1] = ffma2(pv, w.y, a[2 * q + 1]);
                    }
                }
                u64* Xu = (u64*)(sm + OFF_X) + n * 8 + bbp;
#pragma unroll
                for (int s = 0; s < 10; ++s) Xu[s * XPLANE] = a[s];
            }
            __syncthreads();

            const u64* xbase = (const u64*)(sm + OFF_X) + txh * XPLANE + bpx;
            if (r5) gemm_part<18, 5>(acc, xbase, ty);
            else    gemm_part<18, 4>(acc, xbase, ty);
            __syncthreads();

            stageA<34>(Ag, e, 36, t);
            __syncthreads();

            if (r5) gemm_part<17, 5>(acc, xbase + 36 * 8, ty);
            else    gemm_part<17, 4>(acc, xbase + 36 * 8, ty);
            __syncthreads();
        }

        // ---- write a_in into X planes ----
        {
            u64* Xu = (u64*)(sm + OFF_X) + txh * XPLANE + bpx;
#pragma unroll
            for (int i = 0; i < 4; ++i) {
                int row = ty + 16 * i;
#pragma unroll
                for (int j = 0; j < 5; ++j)
                    Xu[j * (2 * XPLANE) + row * 8] = acc[i][j];
            }
            if (r5) {
                int row = 64 + ty;
#pragma unroll
                for (int j = 0; j < 5; ++j)
                    Xu[j * (2 * XPLANE) + row * 8] = acc[4][j];
            }
        }
        __syncthreads();

        // ---- gates (batch-paired, no operand packing) ----
#pragma unroll 1
        for (int task = t; task < 560; task += TPB) {
            int n = task >> 3, bbp = task & 7;
            const u64* Xu = (const u64*)(sm + OFF_X) + n * 8 + bbp;
            u64* Pu = (u64*)(sm + OFF_P) + n * 8 + bbp;

            // r gate
            u64 g[10];
#pragma unroll
            for (int s = 0; s < 10; ++s)
                g[s] = ((const u64*)(sm + OFF_BR))[s];
            {
                const ulonglong2* W = (const ulonglong2*)(sm + OFF_WR);
#pragma unroll
                for (int j = 0; j < 10; ++j) {
                    u64 op = Xu[j * XPLANE];
#pragma unroll
                    for (int q = 0; q < 5; ++q) {
                        ulonglong2 w = W[j * 5 + q];
                        g[2 * q]     = ffma2(op, w.x, g[2 * q]);
                        g[2 * q + 1] = ffma2(op, w.y, g[2 * q + 1]);
                    }
                }
#pragma unroll
                for (int j = 0; j < 10; ++j) {
                    u64 op = Pu[j * PPLANE];
#pragma unroll
                    for (int q = 0; q < 5; ++q) {
                        ulonglong2 w = W[(10 + j) * 5 + q];
                        g[2 * q]     = ffma2(op, w.x, g[2 * q]);
                        g[2 * q + 1] = ffma2(op, w.y, g[2 * q + 1]);
                    }
                }
            }
            // rp = sigmoid(r) * prop
            u64 rp[10];
#pragma unroll
            for (int s = 0; s < 10; ++s) {
                float x, y;
                unpack2(g[s], x, y);
                rp[s] = mul2(packxy(sigf(x), sigf(y)), Pu[s * PPLANE]);
            }
            // h_hat pre-activation into g
#pragma unroll
            for (int s = 0; s < 10; ++s)
                g[s] = ((const u64*)(sm + OFF_BH))[s];
            {
                const ulonglong2* W = (const ulonglong2*)(sm + OFF_WH);
#pragma unroll
                for (int j = 0; j < 10; ++j) {
                    u64 op = Xu[j * XPLANE];
#pragma unroll
                    for (int q = 0; q < 5; ++q) {
                        ulonglong2 w = W[j * 5 + q];
                        g[2 * q]     = ffma2(op, w.x, g[2 * q]);
                        g[2 * q + 1] = ffma2(op, w.y, g[2 * q + 1]);
                    }
                }
#pragma unroll
                for (int j = 0; j < 10; ++j) {
                    u64 op = rp[j];
#pragma unroll
                    for (int q = 0; q < 5; ++q) {
                        ulonglong2 w = W[(10 + j) * 5 + q];
                        g[2 * q]     = ffma2(op, w.x, g[2 * q]);
                        g[2 * q + 1] = ffma2(op, w.y, g[2 * q + 1]);
                    }
                }
            }
            // g := tanh(g)
#pragma unroll
            for (int s = 0; s < 10; ++s) {
                float x, y;
                unpack2(g[s], x, y);
                g[s] = packxy(tanh_(x), tanh_(y));
            }
            // z gate into rp (registers reused)
#pragma unroll
            for (int s = 0; s < 10; ++s)
                rp[s] = ((const u64*)(sm + OFF_BZ))[s];
            {
                const ulonglong2* W = (const ulonglong2*)(sm + OFF_WZ);
#pragma unroll
                for (int j = 0; j < 10; ++j) {
                    u64 op = Xu[j * XPLANE];
#pragma unroll
                    for (int q = 0; q < 5; ++q) {
                        ulonglong2 w = W[j * 5 + q];
                        rp[2 * q]     = ffma2(op, w.x, rp[2 * q]);
                        rp[2 * q + 1] = ffma2(op, w.y, rp[2 * q + 1]);
                    }
                }
#pragma unroll
                for (int j = 0; j < 10; ++j) {
                    u64 op = Pu[j * PPLANE];
#pragma unroll
                    for (int q = 0; q < 5; ++q) {
                        ulonglong2 w = W[(10 + j) * 5 + q];
                        rp[2 * q]     = ffma2(op, w.x, rp[2 * q]);
                        rp[2 * q + 1] = ffma2(op, w.y, rp[2 * q + 1]);
                    }
                }
            }
            // update: prop = prop + z*(h - prop)
#pragma unroll
            for (int s = 0; s < 10; ++s) {
                float zl, zh, hl, hh, pl, ph;
                unpack2(rp[s], zl, zh);
                unpack2(g[s], hl, hh);
                unpack2(Pu[s * PPLANE], pl, ph);
                zl = sigf(zl); zh = sigf(zh);
                float ol = pl + zl * (hl - pl);
                float oh = ph + zh * (hh - ph);
                Pu[s * PPLANE] = packxy(ol, oh);
            }
        }
        __syncthreads();
    }

    // ---- output ----
#pragma unroll 1
    for (int i = t; i < BB_ * N_; i += TPB) {
        int bb = i / N_, n = i - bb * N_;
        float an = annotation[b0 * N_ + i];
        float pv[10];
#pragma unroll
        for (int j = 0; j < 10; ++j)
            pv[j] = sm[OFF_P + j * 1120 + n * 16 + bb];
        float o = sm[OFF_BO2];
#pragma unroll 2
        for (int s = 0; s < 10; ++s) {
            float a0 = sm[OFF_BO1 + s];
#pragma unroll
            for (int j = 0; j < 10; ++j)
                a0 += pv[j] * sm[OFF_WO1 + s * 11 + j];
            a0 += an * sm[OFF_WO1 + s * 11 + 10];
            o += tanh_(a0) * sm[OFF_WO2 + s];
        }
        out[b0 * N_ + i] = o;
    }
}

extern "C" void kernel_launch(void* const* d_in, const int* in_sizes, int n_in,
                              void* d_out, int out_size) {
    const float* annotation = (const float*)d_in[0];
    const float* A    = (const float*)d_in[1];
    const float* W_in = (const float*)d_in[2];
    const float* b_in = (const float*)d_in[3];
    const float* Wr   = (const float*)d_in[4];
    const float* br   = (const float*)d_in[5];
    const float* Wz   = (const float*)d_in[6];
    const float* bz   = (const float*)d_in[7];
    const float* Wh   = (const float*)d_in[8];
    const float* bh   = (const float*)d_in[9];
    const float* Wo1  = (const float*)d_in[10];
    const float* bo1  = (const float*)d_in[11];
    const float* Wo2  = (const float*)d_in[12];
    const float* bo2  = (const float*)d_in[13];
    float* out = (float*)d_out;

    const int smem_bytes = SMEM_FLOATS * (int)sizeof(float);
    cudaFuncSetAttribute(ggnn_kernel,
                         cudaFuncAttributeMaxDynamicSharedMemorySize, smem_bytes);
    ggnn_kernel<<<B_ / BB_, TPB, smem_bytes>>>(
        annotation, A, W_in, b_in, Wr, br, Wz, bz, Wh, bh,
        Wo1, bo1, Wo2, bo2, out);
}

// round 7
// speedup vs baseline: 4.8177x; 4.8177x over previous
#include <cuda_runtime.h>

#define TPB 256

constexpr int B_     = 16384;
constexpr int N_     = 70;
constexpr int E_     = 3;
constexpr int S_     = 10;
constexpr int STEPS_ = 5;
constexpr int BB_    = 16;            // batch elements per CTA
constexpr int COLS_  = BB_ * S_;      // 160 scalar columns
constexpr int PAIRS_ = COLS_ / 2;     // 80 f32x2 columns

// ---- shared memory layout (float offsets) ----
constexpr int OFF_X    = 0;                      // 70*160 = 11200
constexpr int OFF_P    = OFF_X + N_ * COLS_;     // d-planes: 10*1120 = 11200
constexpr int OFF_AS   = OFF_P + 10 * 1120;      // A dup chunk 70*36 u64 = 5040 fl
constexpr int OFF_WIN2 = OFF_AS + 5040;          // 27440: [e][d][6] f2 = 360 fl
constexpr int OFF_BIN2 = OFF_WIN2 + 360;         // 27800: 15 f2 = 30
constexpr int OFF_WR2  = 27832;                  // [j][6] f2 = 240 fl
constexpr int OFF_BR2  = OFF_WR2 + 240;          // 28072: 10
constexpr int OFF_WZ2  = 28084;                  // 240
constexpr int OFF_BZ2  = OFF_WZ2 + 240;          // 28324: 10
constexpr int OFF_WH2  = 28336;                  // 240
constexpr int OFF_BH2  = OFF_WH2 + 240;          // 28576: 10
constexpr int OFF_WO1  = OFF_BH2 + 10;           // 28586: 110
constexpr int OFF_BO1  = OFF_WO1 + 110;          // 10
constexpr int OFF_WO2  = OFF_BO1 + 10;           // 10
constexpr int OFF_BO2  = OFF_WO2 + 10;           // 1
constexpr int SMEM_FLOATS = OFF_BO2 + 1;         // 28717 -> 114868 B/CTA

typedef unsigned long long u64;

// ---- packed f32x2 helpers ----
__device__ __forceinline__ u64 ffma2(u64 a, u64 b, u64 c) {
    u64 d;
    asm("fma.rn.f32x2 %0, %1, %2, %3;" : "=l"(d) : "l"(a), "l"(b), "l"(c));
    return d;
}
__device__ __forceinline__ u64 pack2(float x) {
    u64 d;
    asm("mov.b64 %0, {%1, %1};" : "=l"(d) : "f"(x));
    return d;
}
__device__ __forceinline__ void unpack2(u64 v, float& x, float& y) {
    asm("mov.b64 {%0, %1}, %2;" : "=f"(x), "=f"(y) : "l"(v));
}

__device__ __forceinline__ float sigf(float x) {
    return __fdividef(1.0f, 1.0f + __expf(-x));
}
__device__ __forceinline__ float tanh_(float x) {
    float e = __expf(-2.0f * x);
    return __fdividef(1.0f - e, 1.0f + e);
}

extern __shared__ float sm[];

// ---- stage A[:, e*70+k0 : +35] DUPLICATED into SMEM, row stride 36 u64 ----
// kk==35 lane is zero padding (chunk-edge pair contributes 0).
__device__ __forceinline__ void stageAdup(const float* __restrict__ Ag, int e,
                                          int k0, int t) {
    u64* AsD = (u64*)(sm + OFF_AS);
#pragma unroll 1
    for (int i = t; i < 70 * 36; i += TPB) {
        int row = i / 36, kk = i - row * 36;
        float a = (kk < 35) ? Ag[row * 210 + e * 70 + k0 + kk] : 0.0f;
        AsD[i] = pack2(a);
    }
}

__global__ void __launch_bounds__(TPB, 2) ggnn_kernel(
    const float* __restrict__ annotation, const float* __restrict__ Ag,
    const float* __restrict__ W_in, const float* __restrict__ b_in,
    const float* __restrict__ Wr, const float* __restrict__ br,
    const float* __restrict__ Wz, const float* __restrict__ bz,
    const float* __restrict__ Wh, const float* __restrict__ bh,
    const float* __restrict__ Wo1, const float* __restrict__ bo1,
    const float* __restrict__ Wo2, const float* __restrict__ bo2,
    float* __restrict__ out)
{
    const int t  = threadIdx.x;
    const int b0 = blockIdx.x * BB_;

    // ---- stage paired weight tables (identical to 940us kernel) ----
    for (int i = t; i < 150; i += TPB) {      // WIN2 [e][d][6] (s-pairs)
        int s2 = i % 5, d = (i / 5) % 10, e = i / 50;
        ((float2*)(sm + OFF_WIN2))[e * 60 + d * 6 + s2] =
            make_float2(W_in[(e * 10 + 2 * s2) * 10 + d],
                        W_in[(e * 10 + 2 * s2 + 1) * 10 + d]);
    }
    if (t < 15) {                             // BIN2 [e][s2]
        int s2 = t % 5, e = t / 5;
        ((float2*)(sm + OFF_BIN2))[t] =
            make_float2(b_in[e * 10 + 2 * s2], b_in[e * 10 + 2 * s2 + 1]);
    }
    for (int i = t; i < 100; i += TPB) {      // W{r,z,h}2 [j][6] (s-pairs)
        int s2 = i % 5, j = i / 5;
        ((float2*)(sm + OFF_WR2))[j * 6 + s2] =
            make_float2(Wr[2 * s2 * 20 + j], Wr[(2 * s2 + 1) * 20 + j]);
        ((float2*)(sm + OFF_WZ2))[j * 6 + s2] =
            make_float2(Wz[2 * s2 * 20 + j], Wz[(2 * s2 + 1) * 20 + j]);
        ((float2*)(sm + OFF_WH2))[j * 6 + s2] =
            make_float2(Wh[2 * s2 * 20 + j], Wh[(2 * s2 + 1) * 20 + j]);
    }
    if (t < 5) {
        ((float2*)(sm + OFF_BR2))[t] = make_float2(br[2 * t], br[2 * t + 1]);
        ((float2*)(sm + OFF_BZ2))[t] = make_float2(bz[2 * t], bz[2 * t + 1]);
        ((float2*)(sm + OFF_BH2))[t] = make_float2(bh[2 * t], bh[2 * t + 1]);
    }
    for (int i = t; i < 110; i += TPB) sm[OFF_WO1 + i] = Wo1[i];
    if (t < 10) { sm[OFF_BO1 + t] = bo1[t]; sm[OFF_WO2 + t] = Wo2[t]; }
    if (t == 0) sm[OFF_BO2] = bo2[0];

    // ---- prop init: P[0][idx] = ann, P[1..9][idx] = 0 ----
    for (int i = t; i < BB_ * N_; i += TPB) {
        float a = annotation[b0 * N_ + i];
        sm[OFF_P + i] = a;
#pragma unroll
        for (int d = 1; d < S_; ++d) sm[OFF_P + d * 1120 + i] = 0.0f;
    }
    __syncthreads();

    const int tx = t & 15;   // f32x2 column group
    const int ty = t >> 4;   // row group
    const bool has5 = (ty < 6);

    u64 acc[5][5];

#pragma unroll 1
    for (int step = 0; step < STEPS_; ++step) {
#pragma unroll
        for (int i = 0; i < 5; ++i)
#pragma unroll
            for (int j = 0; j < 5; ++j) acc[i][j] = 0ull;

#pragma unroll 1
        for (int e = 0; e < 3; ++e) {
            // ---- stage A chunk0 (dup) + build X (disjoint writes) ----
            stageAdup(Ag, e, 0, t);
            // ---- build X[n][bb*10+s] = ins (identical to 940us kernel) ----
#pragma unroll 1
            for (int task = t; task < BB_ * N_; task += TPB) {
                int bb = task & 15, n = task >> 4;
                int idx = bb * N_ + n;
                const u64* B2 = (const u64*)(sm + OFF_BIN2) + e * 5;
                u64 a0 = B2[0], a1 = B2[1], a2 = B2[2], a3 = B2[3], a4 = B2[4];
                const float* Wb = sm + OFF_WIN2 + e * 120;
#pragma unroll
                for (int d = 0; d < 10; ++d) {
                    u64 p2 = pack2(sm[OFF_P + d * 1120 + idx]);
                    ulonglong2 wa = *(const ulonglong2*)(Wb + d * 12);
                    ulonglong2 wb = *(const ulonglong2*)(Wb + d * 12 + 4);
                    u64 wc = *(const u64*)(Wb + d * 12 + 8);
                    a0 = ffma2(p2, wa.x, a0);
                    a1 = ffma2(p2, wa.y, a1);
                    a2 = ffma2(p2, wb.x, a2);
                    a3 = ffma2(p2, wb.y, a3);
                    a4 = ffma2(p2, wc, a4);
                }
                u64* xo = (u64*)(sm + OFF_X + n * COLS_ + bb * S_);
                xo[0] = a0; xo[1] = a1; xo[2] = a2; xo[3] = a3; xo[4] = a4;
            }
            __syncthreads();

            // ---- GEMM over the two 35-k chunks; A is a direct u64 operand --
#pragma unroll 1
            for (int chunk = 0; chunk < 2; ++chunk) {
                if (chunk == 1) {
                    stageAdup(Ag, e, 35, t);
                    __syncthreads();
                }
                const int kbase = chunk * 35;
                const u64* AsD = (const u64*)(sm + OFF_AS);
                const u64* Xb  = (const u64*)(sm + OFF_X);
                const int r0 = ty * 36;
                const int r4 = (64 + ty) * 36;
#pragma unroll 1
                for (int k2 = 0; k2 < 18; ++k2) {
                    const int kk = 2 * k2;
                    const u64* x0 = Xb + (kbase + kk) * PAIRS_ + tx;
                    u64 xE[5], xO[5];
#pragma unroll
                    for (int j = 0; j < 5; ++j) {
                        xE[j] = x0[16 * j];
                        xO[j] = x0[PAIRS_ + 16 * j];
                    }
#pragma unroll
                    for (int i = 0; i < 4; ++i) {
                        ulonglong2 a01 =
                            *(const ulonglong2*)(AsD + r0 + i * (16 * 36) + kk);
#pragma unroll
                        for (int j = 0; j < 5; ++j)
                            acc[i][j] = ffma2(a01.x, xE[j], acc[i][j]);
#pragma unroll
                        for (int j = 0; j < 5; ++j)
                            acc[i][j] = ffma2(a01.y, xO[j], acc[i][j]);
                    }
                    if (has5) {
                        ulonglong2 a01 = *(const ulonglong2*)(AsD + r4 + kk);
#pragma unroll
                        for (int j = 0; j < 5; ++j)
                            acc[4][j] = ffma2(a01.x, xE[j], acc[4][j]);
#pragma unroll
                        for (int j = 0; j < 5; ++j)
                            acc[4][j] = ffma2(a01.y, xO[j], acc[4][j]);
                    }
                }
                __syncthreads();
            }
        }

        // ---- write a_in into X buffer (identical to 940us kernel) ----
#pragma unroll
        for (int i = 0; i < 4; ++i) {
            int n = ty + 16 * i;
#pragma unroll
            for (int j = 0; j < 5; ++j)
                *(u64*)(sm + OFF_X + n * COLS_ + 2 * (tx + 16 * j)) = acc[i][j];
        }
        if (has5) {
            int n = 64 + ty;
#pragma unroll
            for (int j = 0; j < 5; ++j)
                *(u64*)(sm + OFF_X + n * COLS_ + 2 * (tx + 16 * j)) = acc[4][j];
        }
        __syncthreads();

        // ---- gates: 2 batch elements per task (identical to 940us kernel) --
#pragma unroll 1
        for (int task = t; task < 8 * N_; task += TPB) {
            int bb0 = (task & 7) * 2, n = task >> 3;
            int idx0 = bb0 * N_ + n, idx1 = idx0 + N_;
            float pv0[10], pv1[10], av0[10], av1[10];
#pragma unroll
            for (int d = 0; d < 10; ++d) {
                pv0[d] = sm[OFF_P + d * 1120 + idx0];
                pv1[d] = sm[OFF_P + d * 1120 + idx1];
            }
            {
                const u64* xr = (const u64*)(sm + OFF_X) + n * PAIRS_ + bb0 * 5;
#pragma unroll
                for (int s2 = 0; s2 < 5; ++s2) {
                    unpack2(xr[s2],     av0[2 * s2], av0[2 * s2 + 1]);
                    unpack2(xr[5 + s2], av1[2 * s2], av1[2 * s2 + 1]);
                }
            }
            // r gate
            u64 r0a[5], r1a[5];
#pragma unroll
            for (int s2 = 0; s2 < 5; ++s2) {
                u64 b = ((const u64*)(sm + OFF_BR2))[s2];
                r0a[s2] = b; r1a[s2] = b;
            }
            const float* WRb = sm + OFF_WR2;
#pragma unroll
            for (int j = 0; j < 20; ++j) {
                u64 o0 = pack2(j < 10 ? av0[j] : pv0[j - 10]);
                u64 o1 = pack2(j < 10 ? av1[j] : pv1[j - 10]);
                ulonglong2 wa = *(const ulonglong2*)(WRb + j * 12);
                ulonglong2 wb = *(const ulonglong2*)(WRb + j * 12 + 4);
                u64 wc = *(const u64*)(WRb + j * 12 + 8);
                r0a[0] = ffma2(o0, wa.x, r0a[0]); r1a[0] = ffma2(o1, wa.x, r1a[0]);
                r0a[1] = ffma2(o0, wa.y, r0a[1]); r1a[1] = ffma2(o1, wa.y, r1a[1]);
                r0a[2] = ffma2(o0, wb.x, r0a[2]); r1a[2] = ffma2(o1, wb.x, r1a[2]);
                r0a[3] = ffma2(o0, wb.y, r0a[3]); r1a[3] = ffma2(o1, wb.y, r1a[3]);
                r0a[4] = ffma2(o0, wc,   r0a[4]); r1a[4] = ffma2(o1, wc,   r1a[4]);
            }
            float rp0[10], rp1[10];
#pragma unroll
            for (int s2 = 0; s2 < 5; ++s2) {
                float x, y;
                unpack2(r0a[s2], x, y);
                rp0[2 * s2] = sigf(x) * pv0[2 * s2];
                rp0[2 * s2 + 1] = sigf(y) * pv0[2 * s2 + 1];
                unpack2(r1a[s2], x, y);
                rp1[2 * s2] = sigf(x) * pv1[2 * s2];
                rp1[2 * s2 + 1] = sigf(y) * pv1[2 * s2 + 1];
            }
            // z and h_hat
            u64 z0a[5], z1a[5], h0a[5], h1a[5];
#pragma unroll
            for (int s2 = 0; s2 < 5; ++s2) {
                u64 bz2 = ((const u64*)(sm + OFF_BZ2))[s2];
                u64 bh2 = ((const u64*)(sm + OFF_BH2))[s2];
                z0a[s2] = bz2; z1a[s2] = bz2;
                h0a[s2] = bh2; h1a[s2] = bh2;
            }
            const float* WZb = sm + OFF_WZ2;
            const float* WHb = sm + OFF_WH2;
#pragma unroll
            for (int j = 0; j < 20; ++j) {
                u64 o0 = pack2(j < 10 ? av0[j] : pv0[j - 10]);
                u64 o1 = pack2(j < 10 ? av1[j] : pv1[j - 10]);
                u64 q0 = (j < 10) ? o0 : pack2(rp0[j - 10]);
                u64 q1 = (j < 10) ? o1 : pack2(rp1[j - 10]);
                ulonglong2 za = *(const ulonglong2*)(WZb + j * 12);
                ulonglong2 zb = *(const ulonglong2*)(WZb + j * 12 + 4);
                u64 zc = *(const u64*)(WZb + j * 12 + 8);
                ulonglong2 ha = *(const ulonglong2*)(WHb + j * 12);
                ulonglong2 hb = *(const ulonglong2*)(WHb + j * 12 + 4);
                u64 hc = *(const u64*)(WHb + j * 12 + 8);
                z0a[0] = ffma2(o0, za.x, z0a[0]); z1a[0] = ffma2(o1, za.x, z1a[0]);
                z0a[1] = ffma2(o0, za.y, z0a[1]); z1a[1] = ffma2(o1, za.y, z1a[1]);
                z0a[2] = ffma2(o0, zb.x, z0a[2]); z1a[2] = ffma2(o1, zb.x, z1a[2]);
                z0a[3] = ffma2(o0, zb.y, z0a[3]); z1a[3] = ffma2(o1, zb.y, z1a[3]);
                z0a[4] = ffma2(o0, zc,   z0a[4]); z1a[4] = ffma2(o1, zc,   z1a[4]);
                h0a[0] = ffma2(q0, ha.x, h0a[0]); h1a[0] = ffma2(q1, ha.x, h1a[0]);
                h0a[1] = ffma2(q0, ha.y, h0a[1]); h1a[1] = ffma2(q1, ha.y, h1a[1]);
                h0a[2] = ffma2(q0, hb.x, h0a[2]); h1a[2] = ffma2(q1, hb.x, h1a[2]);
                h0a[3] = ffma2(q0, hb.y, h0a[3]); h1a[3] = ffma2(q1, hb.y, h1a[3]);
                h0a[4] = ffma2(q0, hc,   h0a[4]); h1a[4] = ffma2(q1, hc,   h1a[4]);
            }
#pragma unroll
            for (int s2 = 0; s2 < 5; ++s2) {
                float zx, zy, hx, hy;
                unpack2(z0a[s2], zx, zy);
                unpack2(h0a[s2], hx, hy);
                zx = sigf(zx); zy = sigf(zy);
                hx = tanh_(hx); hy = tanh_(hy);
                sm[OFF_P + (2 * s2) * 1120 + idx0] =
                    pv0[2 * s2] + zx * (hx - pv0[2 * s2]);
                sm[OFF_P + (2 * s2 + 1) * 1120 + idx0] =
                    pv0[2 * s2 + 1] + zy * (hy - pv0[2 * s2 + 1]);
                unpack2(z1a[s2], zx, zy);
                unpack2(h1a[s2], hx, hy);
                zx = sigf(zx); zy = sigf(zy);
                hx = tanh_(hx); hy = tanh_(hy);
                sm[OFF_P + (2 * s2) * 1120 + idx1] =
                    pv1[2 * s2] + zx * (hx - pv1[2 * s2]);
                sm[OFF_P + (2 * s2 + 1) * 1120 + idx1] =
                    pv1[2 * s2 + 1] + zy * (hy - pv1[2 * s2 + 1]);
            }
        }
        __syncthreads();
    }

    // ---- output (identical to 940us kernel) ----
#pragma unroll 1
    for (int task = t; task < BB_ * N_; task += TPB) {
        int bb = task / N_, n = task - bb * N_;
        int idx = bb * N_ + n;
        float an = annotation[b0 * N_ + idx];
        float o = sm[OFF_BO2];
#pragma unroll 2
        for (int s = 0; s < 10; ++s) {
            float a0 = sm[OFF_BO1 + s];
#pragma unroll
            for (int j = 0; j < 10; ++j)
                a0 += sm[OFF_P + j * 1120 + idx] * sm[OFF_WO1 + s * 11 + j];
            a0 += an * sm[OFF_WO1 + s * 11 + 10];
            o += tanh_(a0) * sm[OFF_WO2 + s];
        }
        out[b0 * N_ + idx] = o;
    }
}

extern "C" void kernel_launch(void* const* d_in, const int* in_sizes, int n_in,
                              void* d_out, int out_size) {
    const float* annotation = (const float*)d_in[0];
    const float* A    = (const float*)d_in[1];
    const float* W_in = (const float*)d_in[2];
    const float* b_in = (const float*)d_in[3];
    const float* Wr   = (const float*)d_in[4];
    const float* br   = (const float*)d_in[5];
    const float* Wz   = (const float*)d_in[6];
    const float* bz   = (const float*)d_in[7];
    const float* Wh   = (const float*)d_in[8];
    const float* bh   = (const float*)d_in[9];
    const float* Wo1  = (const float*)d_in[10];
    const float* bo1  = (const float*)d_in[11];
    const float* Wo2  = (const float*)d_in[12];
    const float* bo2  = (const float*)d_in[13];
    float* out = (float*)d_out;

    const int smem_bytes = SMEM_FLOATS * (int)sizeof(float);
    cudaFuncSetAttribute(ggnn_kernel,
                         cudaFuncAttributeMaxDynamicSharedMemorySize, smem_bytes);
    ggnn_kernel<<<B_ / BB_, TPB, smem_bytes>>>(
        annotation, A, W_in, b_in, Wr, br, Wz, bz, Wh, bh,
        Wo1, bo1, Wo2, bo2, out);
}